// round 2
// baseline (speedup 1.0000x reference)
#include <cuda_runtime.h>
#include <math.h>

#define CDIV(a,b) (((a)+(b)-1)/(b))
#define N_ANCH 76725
#define N_SORT 131072
#define KTOP   1000

// ---------------- scratch (static device globals; no allocation) -------------
__device__ float g_bufA[256*6400];
__device__ float g_bufB[256*6400];
__device__ float g_cls[720*8525];      // head logits per level, [c][h][w] concat
__device__ float g_reg[36*8525];
__device__ float g_scores[N_ANCH];
__device__ int   g_arg[N_ANCH];
__device__ float4 g_loc[N_ANCH];
__device__ unsigned long long g_keys[N_SORT];
__device__ float4 g_selBox[KTOP];
__device__ float  g_topVal[KTOP];
__device__ int    g_selCls[KTOP];
__device__ unsigned char g_keep[KTOP];

// ---------------- 3x3 SAME conv, Cin=256, register-tiled ---------------------
// block: 256 threads = 16 pixel-threads (2x2 px each, 8x8 tile) x 16 cout-threads
// (4 couts each, 64-cout block). smem: 8-cin input tile + weights chunk.
__global__ __launch_bounds__(256)
void conv3x3_k(const float* __restrict__ in, const float* __restrict__ wgt,
               const float* __restrict__ bias, float* __restrict__ out,
               int H, int W, int Cout, int relu)
{
    const int HW = H * W;
    const int tid = threadIdx.x;
    const int p = tid & 15, q = tid >> 4;
    const int x0 = blockIdx.x * 8, y0 = blockIdx.y * 8;
    const int cb = blockIdx.z * 64;

    __shared__ __align__(16) float s_in[8][10][12];
    __shared__ __align__(16) float s_w[8][9][64];

    float acc[2][2][4] = {};
    const int pyb = (p >> 2) * 2, pxb = (p & 3) * 2;

    for (int cinBase = 0; cinBase < 256; cinBase += 8) {
        // input tile 8cin x 10x10 (with halo, zero-pad OOB)
        for (int i = tid; i < 800; i += 256) {
            int ci = i / 100, r = i % 100, dy = r / 10, dx = r % 10;
            int gy = y0 - 1 + dy, gx = x0 - 1 + dx;
            float v = 0.f;
            if (gy >= 0 && gy < H && gx >= 0 && gx < W)
                v = in[(cinBase + ci) * HW + gy * W + gx];
            s_in[ci][dy][dx] = v;
        }
        // weights 64cout x 8cin x 9  ->  s_w[ci][k][co]
        for (int i = tid; i < 4608; i += 256) {
            int co = i / 72, cik = i % 72, ci = cik / 9, kk = cik % 9;
            int cog = cb + co;
            float v = 0.f;
            if (cog < Cout) v = wgt[(cog * 256 + cinBase + ci) * 9 + kk];
            s_w[ci][kk][co] = v;
        }
        __syncthreads();
        #pragma unroll
        for (int ci = 0; ci < 8; ci++) {
            #pragma unroll
            for (int ky = 0; ky < 3; ky++)
            #pragma unroll
            for (int kx = 0; kx < 3; kx++) {
                const float4 wv = *(const float4*)&s_w[ci][ky * 3 + kx][q * 4];
                #pragma unroll
                for (int py = 0; py < 2; py++)
                #pragma unroll
                for (int px = 0; px < 2; px++) {
                    float iv = s_in[ci][pyb + py + ky][pxb + px + kx];
                    acc[py][px][0] += iv * wv.x;
                    acc[py][px][1] += iv * wv.y;
                    acc[py][px][2] += iv * wv.z;
                    acc[py][px][3] += iv * wv.w;
                }
            }
        }
        __syncthreads();
    }
    #pragma unroll
    for (int j = 0; j < 4; j++) {
        int co = cb + q * 4 + j;
        if (co >= Cout) break;
        float bv = bias[co];
        #pragma unroll
        for (int py = 0; py < 2; py++) {
            int y = y0 + pyb + py;
            if (y >= H) continue;
            #pragma unroll
            for (int px = 0; px < 2; px++) {
                int x = x0 + pxb + px;
                if (x >= W) continue;
                float v = acc[py][px][j] + bv;
                if (relu) v = fmaxf(v, 0.f);
                out[co * HW + y * W + x] = v;
            }
        }
    }
}

// ---------------- per-anchor scores + argmax + sort keys + loc repack --------
__device__ __forceinline__ void anchor_split(int idx, int& L, int& p, int& a, int& Wd)
{
    const int aoff[6] = {0, 57600, 72000, 75600, 76500, 76725};
    const int Ws[5] = {80, 40, 20, 10, 5};
    L = 0;
    while (L < 4 && idx >= aoff[L + 1]) L++;
    int rel = idx - aoff[L];
    p = rel / 9; a = rel - p * 9; Wd = Ws[L];
}

__global__ void score_key_k(const float* __restrict__ cls_raw,
                            const float* __restrict__ reg_raw,
                            float* __restrict__ scores, int* __restrict__ arg,
                            float4* __restrict__ loc,
                            unsigned long long* __restrict__ keys)
{
    int idx = blockIdx.x * blockDim.x + threadIdx.x;
    if (idx >= N_SORT) return;
    if (idx >= N_ANCH) { keys[idx] = 0xFFFFFFFFFFFFFFFFULL; return; }

    const int cum[5] = {0, 6400, 8000, 8400, 8500};
    int L, p, a, W;
    anchor_split(idx, L, p, a, W);
    int HW = W * W;

    // argmax must be over SIGMOID values (reference argmaxes post-sigmoid,
    // where saturation to 1.0f creates ties broken by first index).
    const float* cb = cls_raw + 720 * cum[L] + (a * 80) * HW + p;
    float best = 1.f / (1.f + expf(-cb[0]));
    int barg = 0;
    for (int c = 1; c < 80; c++) {
        float s = 1.f / (1.f + expf(-cb[c * HW]));
        if (s > best) { best = s; barg = c; }
    }
    float masked = (best > 0.05f) ? best : -1.0f;
    scores[idx] = masked;
    arg[idx] = barg;

    const float* rb = reg_raw + 36 * cum[L] + (a * 4) * HW + p;
    loc[idx] = make_float4(rb[0], rb[HW], rb[2 * HW], rb[3 * HW]);

    unsigned u = __float_as_uint(masked);
    u = (u & 0x80000000u) ? ~u : (u | 0x80000000u);
    keys[idx] = (((unsigned long long)(~u)) << 32) | (unsigned)idx;  // asc sort = desc score, asc idx
}

// ---------------- bitonic sort (ascending) over 2^17 keys -------------------
__global__ void bitonic_global_k(unsigned long long* __restrict__ keys, int k, int j)
{
    int i = blockIdx.x * blockDim.x + threadIdx.x;
    int ixj = i ^ j;
    if (ixj > i) {
        unsigned long long a = keys[i], b = keys[ixj];
        bool up = ((i & k) == 0);
        if ((a > b) == up) { keys[i] = b; keys[ixj] = a; }
    }
}

__global__ __launch_bounds__(1024)
void bitonic_shared_k(unsigned long long* __restrict__ keys, int k, int jstart)
{
    __shared__ unsigned long long s[2048];
    int tid = threadIdx.x;
    int base = blockIdx.x * 2048;
    s[tid] = keys[base + tid];
    s[tid + 1024] = keys[base + tid + 1024];
    __syncthreads();
    for (int j = jstart; j >= 1; j >>= 1) {
        #pragma unroll
        for (int h = 0; h < 2; h++) {
            int l = tid + h * 1024;
            int ixj = l ^ j;
            if (ixj > l) {
                unsigned long long a = s[l], b = s[ixj];
                bool up = (((base + l) & k) == 0);
                if ((a > b) == up) { s[l] = b; s[ixj] = a; }
            }
        }
        __syncthreads();
    }
    keys[base + tid] = s[tid];
    keys[base + tid + 1024] = s[tid + 1024];
}

// ---------------- decode top-1000 boxes --------------------------------------
__global__ void decode_k(const unsigned long long* __restrict__ keys,
                         const float* __restrict__ scores,
                         const int* __restrict__ arg,
                         const float4* __restrict__ loc,
                         float4* __restrict__ selBox, float* __restrict__ topVal,
                         int* __restrict__ selCls)
{
    int r = blockIdx.x * blockDim.x + threadIdx.x;
    if (r >= KTOP) return;
    int idx = (int)(keys[r] & 0xFFFFFFFFULL);
    float val = scores[idx];
    topVal[r] = val;
    selCls[r] = arg[idx];

    const int strides[5] = {8, 16, 32, 64, 128};
    const int sizes[5] = {32, 64, 128, 256, 512};
    int L, p, a, W;
    anchor_split(idx, L, p, a, W);
    int y = p / W, x = p - y * W;
    int ri = a / 3, si = a - ri * 3;
    const float ratios[3] = {0.5f, 1.0f, 2.0f};
    const float scales[3] = {1.0f, 1.2599210498948732f, 1.5874010519681994f};
    float sq = sqrtf(ratios[ri]);
    float ws = (float)sizes[L] * scales[si] / sq;
    float hs = (float)sizes[L] * scales[si] * sq;
    float st = (float)strides[L];
    float cx = ((float)x + 0.5f) * st;
    float cy = ((float)y + 0.5f) * st;

    float4 l = loc[idx];
    float dx = l.x * 0.1f, dy = l.y * 0.1f, dw = l.z * 0.2f, dh = l.w * 0.2f;
    float pcx = cx + dx * ws, pcy = cy + dy * hs;
    float pw = expf(dw) * ws, ph = expf(dh) * hs;
    float bx1 = fminf(fmaxf(pcx - 0.5f * pw, 0.f), 640.f);
    float by1 = fminf(fmaxf(pcy - 0.5f * ph, 0.f), 640.f);
    float bx2 = fminf(fmaxf(pcx + 0.5f * pw, 0.f), 640.f);
    float by2 = fminf(fmaxf(pcy + 0.5f * ph, 0.f), 640.f);
    selBox[r] = make_float4(bx1, by1, bx2, by2);
}

// ---------------- greedy sequential NMS (single block) ----------------------
__global__ __launch_bounds__(1024)
void nms_k(const float4* __restrict__ boxes, const float* __restrict__ vals,
           unsigned char* __restrict__ keepOut)
{
    __shared__ float4 sb[KTOP];
    __shared__ float sarea[KTOP];
    __shared__ unsigned char sk[KTOP];
    int t = threadIdx.x;
    if (t < KTOP) {
        float4 b = boxes[t];
        sb[t] = b;
        sarea[t] = fmaxf(b.z - b.x, 0.f) * fmaxf(b.w - b.y, 0.f);
        sk[t] = (vals[t] > 0.f) ? 1 : 0;
    }
    __syncthreads();
    for (int i = 0; i < KTOP; i++) {
        if (sk[i]) {   // uniform read (all writes are sync'd)
            if (t > i && t < KTOP && sk[t]) {
                float4 bi = sb[i], bj = sb[t];
                float xx1 = fmaxf(bi.x, bj.x), yy1 = fmaxf(bi.y, bj.y);
                float xx2 = fminf(bi.z, bj.z), yy2 = fminf(bi.w, bj.w);
                float inter = fmaxf(xx2 - xx1, 0.f) * fmaxf(yy2 - yy1, 0.f);
                float iou = inter / (sarea[i] + sarea[t] - inter + 1e-8f);
                if (iou > 0.5f) sk[t] = 0;
            }
            __syncthreads();
        }
    }
    __syncthreads();
    if (t < KTOP) keepOut[t] = sk[t];
}

// ---------------- pack output: scores | classes | boxes | keep ---------------
__global__ void output_k(const float* __restrict__ vals, const int* __restrict__ cls,
                         const float4* __restrict__ boxes,
                         const unsigned char* __restrict__ keep,
                         float* __restrict__ out, int out_size)
{
    int r = blockIdx.x * blockDim.x + threadIdx.x;
    if (r >= KTOP) return;
    bool k = keep[r] != 0;
    float4 b = boxes[r];
    if (r < out_size) out[r] = k ? vals[r] : 0.f;
    if (1000 + r < out_size) out[1000 + r] = (float)cls[r];
    if (2000 + 4 * r + 3 < out_size) {
        out[2000 + 4 * r + 0] = k ? b.x : 0.f;
        out[2000 + 4 * r + 1] = k ? b.y : 0.f;
        out[2000 + 4 * r + 2] = k ? b.z : 0.f;
        out[2000 + 4 * r + 3] = k ? b.w : 0.f;
    }
    if (6000 + r < out_size) out[6000 + r] = k ? 1.f : 0.f;
}

// ---------------- host orchestration ----------------------------------------
extern "C" void kernel_launch(void* const* d_in, const int* in_sizes, int n_in,
                              void* d_out, int out_size)
{
    (void)in_sizes; (void)n_in;
    const float* feats[5] = {(const float*)d_in[0], (const float*)d_in[1],
                             (const float*)d_in[2], (const float*)d_in[3],
                             (const float*)d_in[4]};
    const float* cls_w  = (const float*)d_in[5];
    const float* cls_b  = (const float*)d_in[6];
    const float* cls_hw = (const float*)d_in[7];
    const float* cls_hb = (const float*)d_in[8];
    const float* reg_w  = (const float*)d_in[9];
    const float* reg_b  = (const float*)d_in[10];
    const float* reg_hw = (const float*)d_in[11];
    const float* reg_hb = (const float*)d_in[12];

    float *bufA, *bufB, *clsR, *regR, *scores, *topVal;
    int *arg, *selCls;
    float4 *loc, *selBox;
    unsigned long long* keys;
    unsigned char* keep;
    cudaGetSymbolAddress((void**)&bufA, g_bufA);
    cudaGetSymbolAddress((void**)&bufB, g_bufB);
    cudaGetSymbolAddress((void**)&clsR, g_cls);
    cudaGetSymbolAddress((void**)&regR, g_reg);
    cudaGetSymbolAddress((void**)&scores, g_scores);
    cudaGetSymbolAddress((void**)&arg, g_arg);
    cudaGetSymbolAddress((void**)&loc, g_loc);
    cudaGetSymbolAddress((void**)&keys, g_keys);
    cudaGetSymbolAddress((void**)&selBox, g_selBox);
    cudaGetSymbolAddress((void**)&topVal, g_topVal);
    cudaGetSymbolAddress((void**)&selCls, g_selCls);
    cudaGetSymbolAddress((void**)&keep, g_keep);

    const int Hs[5]  = {80, 40, 20, 10, 5};
    const int cum[5] = {0, 6400, 8000, 8400, 8500};
    const int LW = 256 * 256 * 9;  // per-layer trunk weight count

    for (int L = 0; L < 5; L++) {
        int H = Hs[L];
        dim3 gt(CDIV(H, 8), CDIV(H, 8), 4);
        // classification tower
        conv3x3_k<<<gt, 256>>>(feats[L], cls_w,          cls_b,       bufA, H, H, 256, 1);
        conv3x3_k<<<gt, 256>>>(bufA,     cls_w + LW,     cls_b + 256, bufB, H, H, 256, 1);
        conv3x3_k<<<gt, 256>>>(bufB,     cls_w + 2 * LW, cls_b + 512, bufA, H, H, 256, 1);
        conv3x3_k<<<gt, 256>>>(bufA,     cls_w + 3 * LW, cls_b + 768, bufB, H, H, 256, 1);
        dim3 gh(CDIV(H, 8), CDIV(H, 8), CDIV(720, 64));
        conv3x3_k<<<gh, 256>>>(bufB, cls_hw, cls_hb, clsR + 720 * cum[L], H, H, 720, 0);
        // regression tower
        conv3x3_k<<<gt, 256>>>(feats[L], reg_w,          reg_b,       bufA, H, H, 256, 1);
        conv3x3_k<<<gt, 256>>>(bufA,     reg_w + LW,     reg_b + 256, bufB, H, H, 256, 1);
        conv3x3_k<<<gt, 256>>>(bufB,     reg_w + 2 * LW, reg_b + 512, bufA, H, H, 256, 1);
        conv3x3_k<<<gt, 256>>>(bufA,     reg_w + 3 * LW, reg_b + 768, bufB, H, H, 256, 1);
        dim3 gr(CDIV(H, 8), CDIV(H, 8), 1);
        conv3x3_k<<<gr, 256>>>(bufB, reg_hw, reg_hb, regR + 36 * cum[L], H, H, 36, 0);
    }

    score_key_k<<<N_SORT / 256, 256>>>(clsR, regR, scores, arg, loc, keys);

    for (int k = 2; k <= N_SORT; k <<= 1) {
        int j = k >> 1;
        for (; j > 1024; j >>= 1)
            bitonic_global_k<<<N_SORT / 256, 256>>>(keys, k, j);
        bitonic_shared_k<<<N_SORT / 2048, 1024>>>(keys, k, j);
    }

    decode_k<<<CDIV(KTOP, 256), 256>>>(keys, scores, arg, loc, selBox, topVal, selCls);
    nms_k<<<1, 1024>>>(selBox, topVal, keep);
    output_k<<<CDIV(KTOP, 256), 256>>>(topVal, selCls, selBox, keep,
                                       (float*)d_out, out_size);
}

// round 4
// speedup vs baseline: 3.1259x; 3.1259x over previous
#include <cuda_runtime.h>
#include <math.h>

#define CDIV(a,b) (((a)+(b)-1)/(b))
#define N_ANCH 76725
#define N_SORT 131072
#define KTOP   1000
#define TS     (256*8525)          // per-tower activation buffer stride (floats)
typedef unsigned long long ull;

// ---------------- scratch (static device globals; no allocation) -------------
__device__ float g_bufA[2*TS];                 // [tower][C=256][HW concat]
__device__ float g_bufB[2*TS];
__device__ float g_wTrunk[2*4*256*9*256];      // [tower][layer][ci][k][co]
__device__ float g_wCls[256*9*768];            // [ci][k][co(pad 768)]
__device__ float g_wReg[256*9*128];            // [ci][k][co(pad 128)]
__device__ float g_cls[720*8525];
__device__ float g_reg[36*8525];
__device__ float g_scores[N_ANCH];
__device__ int   g_arg[N_ANCH];
__device__ float4 g_loc[N_ANCH];
__device__ ull   g_keys[N_SORT];
__device__ float4 g_selBox[KTOP];
__device__ float  g_topVal[KTOP];
__device__ int    g_selCls[KTOP];
__device__ unsigned char g_keep[KTOP];

// ---------------- weight transposes ------------------------------------------
// trunk src: [4][co256][ci256][3][3]  ->  dst [4][ci][k9][co256]
__global__ void transpose_trunk_k(const float* __restrict__ src, float* __restrict__ dst)
{
    int idx = blockIdx.x * blockDim.x + threadIdx.x;
    if (idx >= 4*256*9*256) return;
    int co = idx & 255, r = idx >> 8;
    int kk = r % 9, r2 = r / 9;
    int ci = r2 & 255, layer = r2 >> 8;
    dst[idx] = src[((layer*256 + co)*256 + ci)*9 + kk];
}
// head src: [Cout][ci256][3][3] -> dst [ci][k9][STRIDE] zero-padded
__global__ void transpose_head_k(const float* __restrict__ src, float* __restrict__ dst,
                                 int Cout, int STR)
{
    int idx = blockIdx.x * blockDim.x + threadIdx.x;
    if (idx >= 256*9*STR) return;
    int co = idx % STR, r = idx / STR;
    int kk = r % 9, ci = r / 9;
    dst[idx] = (co < Cout) ? src[((co*256 + ci)*9) + kk] : 0.f;
    if (co < Cout) dst[idx] = src[(co*256 + ci)*9 + kk];
}

// ---------------- packed fp32x2 helpers --------------------------------------
__device__ __forceinline__ void ffma2(ull& d, ull a, ull b) {
    asm("fma.rn.f32x2 %0, %1, %2, %0;" : "+l"(d) : "l"(a), "l"(b));
}
__device__ __forceinline__ ull pack2(float v) {
    ull r; asm("mov.b64 %0, {%1, %1};" : "=l"(r) : "f"(v)); return r;
}
__device__ __forceinline__ float lo32(ull a) { return __uint_as_float((unsigned)a); }
__device__ __forceinline__ float hi32(ull a) { return __uint_as_float((unsigned)(a >> 32)); }

// ---------------- tile/level decode (compile-time tables) --------------------
__device__ __forceinline__ void tile_decode(int t, int& L, int& H, int& hwBase,
                                            int& x0, int& y0)
{
    int tpr;
    if      (t < 100) { L=0; H=80; hwBase=0;    tpr=10; }
    else if (t < 125) { L=1; H=40; hwBase=6400; tpr=5;  t-=100; }
    else if (t < 134) { L=2; H=20; hwBase=8000; tpr=3;  t-=125; }
    else if (t < 138) { L=3; H=10; hwBase=8400; tpr=2;  t-=134; }
    else              { L=4; H=5;  hwBase=8500; tpr=1;  t-=138; }
    x0 = (t % tpr) * 8; y0 = (t / tpr) * 8;
}

// ---------------- conv core: 128co x 8x8px per block, FFMA2 ------------------
// threads 256: p = tid&15 (2x2 px), q = tid>>4 (8 couts)
__device__ __forceinline__ void conv_core(
    const float* __restrict__ in, const float* __restrict__ wT, int STR,
    int coBase, const float* __restrict__ bias, float* __restrict__ out,
    int Cout, int relu, int H, int x0, int y0)
{
    const int W = H, HW = H * W;
    const int tid = threadIdx.x;
    const int p = tid & 15, q = tid >> 4;
    const int pyb = (p >> 2) * 2, pxb = (p & 3) * 2;
    const int coQ = q * 8;

    __shared__ __align__(16) float s_w[8*9*128];
    __shared__ ull s_in2[8*10*14];

    // hoisted fill geometry for input tile (4 items/thread, 800 total)
    int  sAddr[4]; int gInv[4]; bool okL[4], okS[4];
    #pragma unroll
    for (int j = 0; j < 4; j++) {
        int idx = tid + j * 256;
        int ci = idx / 100, r = idx % 100, dy = r / 10, dx = r % 10;
        int gy = y0 - 1 + dy, gx = x0 - 1 + dx;
        okS[j] = idx < 800;
        okL[j] = okS[j] && gy >= 0 && gy < H && gx >= 0 && gx < W;
        gInv[j] = okL[j] ? (ci * HW + gy * W + gx) : 0;
        sAddr[j] = ci * 140 + dy * 14 + dx;
    }
    const int co = tid & 127, half = tid >> 7;

    ull acc[2][2][4] = {};

    for (int cinBase = 0; cinBase < 256; cinBase += 8) {
        // input tile: duplicated float2
        #pragma unroll
        for (int j = 0; j < 4; j++) {
            if (okS[j]) {
                float v = okL[j] ? __ldg(in + gInv[j] + cinBase * HW) : 0.f;
                s_in2[sAddr[j]] = pack2(v);
            }
        }
        // weights: rows = ci*9+k (72 rows), 128 co each, coalesced
        {
            const float* wp = wT + (cinBase * 9 + half) * STR + coBase + co;
            float* sp = s_w + half * 128 + co;
            #pragma unroll
            for (int r = 0; r < 36; r++)
                sp[r * 256] = wp[r * 2 * STR];
        }
        __syncthreads();

        #pragma unroll 1
        for (int ci = 0; ci < 8; ci++) {
            const ull* rowb = s_in2 + ci * 140;
            const float* wcb = s_w + ci * 9 * 128 + coQ;
            #pragma unroll
            for (int ky = 0; ky < 3; ky++) {
                ull iv[2][4];
                #pragma unroll
                for (int r = 0; r < 2; r++)
                    #pragma unroll
                    for (int c = 0; c < 4; c++)
                        iv[r][c] = rowb[(pyb + ky + r) * 14 + pxb + c];
                #pragma unroll
                for (int kx = 0; kx < 3; kx++) {
                    const float* wrow = wcb + (ky * 3 + kx) * 128;
                    ull w0 = *(const ull*)(wrow);
                    ull w1 = *(const ull*)(wrow + 2);
                    ull w2 = *(const ull*)(wrow + 4);
                    ull w3 = *(const ull*)(wrow + 6);
                    #pragma unroll
                    for (int py = 0; py < 2; py++)
                        #pragma unroll
                        for (int px = 0; px < 2; px++) {
                            ffma2(acc[py][px][0], iv[py][px + kx], w0);
                            ffma2(acc[py][px][1], iv[py][px + kx], w1);
                            ffma2(acc[py][px][2], iv[py][px + kx], w2);
                            ffma2(acc[py][px][3], iv[py][px + kx], w3);
                        }
                }
            }
        }
        __syncthreads();
    }

    #pragma unroll
    for (int pr = 0; pr < 4; pr++) {
        int c0 = coBase + coQ + pr * 2, c1 = c0 + 1;
        if (c0 >= Cout) continue;
        float b0 = bias[c0];
        float b1 = (c1 < Cout) ? bias[c1] : 0.f;
        #pragma unroll
        for (int py = 0; py < 2; py++) {
            int y = y0 + pyb + py;
            if (y >= H) continue;
            #pragma unroll
            for (int px = 0; px < 2; px++) {
                int x = x0 + pxb + px;
                if (x >= W) continue;
                float v0 = lo32(acc[py][px][pr]) + b0;
                float v1 = hi32(acc[py][px][pr]) + b1;
                if (relu) { v0 = fmaxf(v0, 0.f); v1 = fmaxf(v1, 0.f); }
                out[c0 * HW + y * W + x] = v0;
                if (c1 < Cout) out[c1 * HW + y * W + x] = v1;
            }
        }
    }
}

// trunk: grid (139 tiles, 2 co-blocks, 2 towers)
__global__ __launch_bounds__(256, 3)
void conv_trunk_k(const float* f0, const float* f1, const float* f2,
                  const float* f3, const float* f4,
                  const float* __restrict__ actIn, float* __restrict__ actOut,
                  const float* __restrict__ wT,
                  const float* __restrict__ biasCls, const float* __restrict__ biasReg,
                  int layer, int isFirst)
{
    int L, H, hwBase, x0, y0;
    tile_decode(blockIdx.x, L, H, hwBase, x0, y0);
    const int tower = blockIdx.z;
    const int coBase = blockIdx.y * 128;
    const float* in;
    if (isFirst) {
        const float* fs[5] = {f0, f1, f2, f3, f4};
        in = fs[L];
    } else {
        in = actIn + tower * TS + hwBase * 256;
    }
    const float* w = wT + (tower * 4 + layer) * (256*9*256);
    const float* b = (tower ? biasReg : biasCls) + layer * 256;
    float* out = actOut + tower * TS + hwBase * 256;
    conv_core(in, w, 256, coBase, b, out, 256, 1, H, x0, y0);
}

// heads: grid (139 tiles, 7): y<6 cls co-blocks, y==6 reg
__global__ __launch_bounds__(256, 3)
void conv_head_k(const float* __restrict__ actIn,
                 float* __restrict__ outCls, float* __restrict__ outReg,
                 const float* __restrict__ wTc, const float* __restrict__ wTr,
                 const float* __restrict__ biasC, const float* __restrict__ biasR)
{
    int L, H, hwBase, x0, y0;
    tile_decode(blockIdx.x, L, H, hwBase, x0, y0);
    const int yy = blockIdx.y;
    if (yy < 6) {
        const float* in = actIn + 0 * TS + hwBase * 256;
        conv_core(in, wTc, 768, yy * 128, biasC, outCls + 720 * hwBase, 720, 0, H, x0, y0);
    } else {
        const float* in = actIn + 1 * TS + hwBase * 256;
        conv_core(in, wTr, 128, 0, biasR, outReg + 36 * hwBase, 36, 0, H, x0, y0);
    }
}

// ---------------- per-anchor scores + argmax + sort keys + loc repack --------
__device__ __forceinline__ void anchor_split(int idx, int& L, int& p, int& a, int& Wd)
{
    const int aoff[6] = {0, 57600, 72000, 75600, 76500, 76725};
    const int Ws[5] = {80, 40, 20, 10, 5};
    L = 0;
    while (L < 4 && idx >= aoff[L + 1]) L++;
    int rel = idx - aoff[L];
    p = rel / 9; a = rel - p * 9; Wd = Ws[L];
}

__global__ void score_key_k(const float* __restrict__ cls_raw,
                            const float* __restrict__ reg_raw,
                            float* __restrict__ scores, int* __restrict__ arg,
                            float4* __restrict__ loc,
                            ull* __restrict__ keys)
{
    int idx = blockIdx.x * blockDim.x + threadIdx.x;
    if (idx >= N_SORT) return;
    if (idx >= N_ANCH) { keys[idx] = 0xFFFFFFFFFFFFFFFFULL; return; }

    const int cum[5] = {0, 6400, 8000, 8400, 8500};
    int L, p, a, W;
    anchor_split(idx, L, p, a, W);
    int HW = W * W;

    // argmax over SIGMOID values (post-sigmoid saturation ties break by first idx)
    const float* cb = cls_raw + 720 * cum[L] + (a * 80) * HW + p;
    float best = 1.f / (1.f + expf(-cb[0]));
    int barg = 0;
    for (int c = 1; c < 80; c++) {
        float s = 1.f / (1.f + expf(-cb[c * HW]));
        if (s > best) { best = s; barg = c; }
    }
    float masked = (best > 0.05f) ? best : -1.0f;
    scores[idx] = masked;
    arg[idx] = barg;

    const float* rb = reg_raw + 36 * cum[L] + (a * 4) * HW + p;
    loc[idx] = make_float4(rb[0], rb[HW], rb[2 * HW], rb[3 * HW]);

    unsigned u = __float_as_uint(masked);
    u = (u & 0x80000000u) ? ~u : (u | 0x80000000u);
    keys[idx] = (((ull)(~u)) << 32) | (unsigned)idx;
}

// ---------------- bitonic sort (ascending) over 2^17 keys -------------------
// full local sort of 2048-chunks: phases k=2..2048 fused
__global__ __launch_bounds__(1024)
void bitonic_local_k(ull* __restrict__ keys)
{
    __shared__ ull s[2048];
    int tid = threadIdx.x;
    int base = blockIdx.x * 2048;
    s[tid] = keys[base + tid];
    s[tid + 1024] = keys[base + tid + 1024];
    __syncthreads();
    for (int k = 2; k <= 2048; k <<= 1) {
        for (int j = k >> 1; j >= 1; j >>= 1) {
            #pragma unroll
            for (int h = 0; h < 2; h++) {
                int l = tid + h * 1024;
                int ixj = l ^ j;
                if (ixj > l) {
                    ull a = s[l], b = s[ixj];
                    bool up = (((base + l) & k) == 0);
                    if ((a > b) == up) { s[l] = b; s[ixj] = a; }
                }
            }
            __syncthreads();
        }
    }
    keys[base + tid] = s[tid];
    keys[base + tid + 1024] = s[tid + 1024];
}

__global__ void bitonic_global_k(ull* __restrict__ keys, int k, int j)
{
    int i = blockIdx.x * blockDim.x + threadIdx.x;
    int ixj = i ^ j;
    if (ixj > i) {
        ull a = keys[i], b = keys[ixj];
        bool up = ((i & k) == 0);
        if ((a > b) == up) { keys[i] = b; keys[ixj] = a; }
    }
}

__global__ __launch_bounds__(1024)
void bitonic_shared_k(ull* __restrict__ keys, int k, int jstart)
{
    __shared__ ull s[2048];
    int tid = threadIdx.x;
    int base = blockIdx.x * 2048;
    s[tid] = keys[base + tid];
    s[tid + 1024] = keys[base + tid + 1024];
    __syncthreads();
    for (int j = jstart; j >= 1; j >>= 1) {
        #pragma unroll
        for (int h = 0; h < 2; h++) {
            int l = tid + h * 1024;
            int ixj = l ^ j;
            if (ixj > l) {
                ull a = s[l], b = s[ixj];
                bool up = (((base + l) & k) == 0);
                if ((a > b) == up) { s[l] = b; s[ixj] = a; }
            }
        }
        __syncthreads();
    }
    keys[base + tid] = s[tid];
    keys[base + tid + 1024] = s[tid + 1024];
}

// ---------------- decode top-1000 boxes --------------------------------------
__global__ void decode_k(const ull* __restrict__ keys,
                         const float* __restrict__ scores,
                         const int* __restrict__ arg,
                         const float4* __restrict__ loc,
                         float4* __restrict__ selBox, float* __restrict__ topVal,
                         int* __restrict__ selCls)
{
    int r = blockIdx.x * blockDim.x + threadIdx.x;
    if (r >= KTOP) return;
    int idx = (int)(keys[r] & 0xFFFFFFFFULL);
    float val = scores[idx];
    topVal[r] = val;
    selCls[r] = arg[idx];

    const int strides[5] = {8, 16, 32, 64, 128};
    const int sizes[5] = {32, 64, 128, 256, 512};
    int L, p, a, W;
    anchor_split(idx, L, p, a, W);
    int y = p / W, x = p - y * W;
    int ri = a / 3, si = a - ri * 3;
    const float ratios[3] = {0.5f, 1.0f, 2.0f};
    const float scales[3] = {1.0f, 1.2599210498948732f, 1.5874010519681994f};
    float sq = sqrtf(ratios[ri]);
    float ws = (float)sizes[L] * scales[si] / sq;
    float hs = (float)sizes[L] * scales[si] * sq;
    float st = (float)strides[L];
    float cx = ((float)x + 0.5f) * st;
    float cy = ((float)y + 0.5f) * st;

    float4 l = loc[idx];
    float dx = l.x * 0.1f, dy = l.y * 0.1f, dw = l.z * 0.2f, dh = l.w * 0.2f;
    float pcx = cx + dx * ws, pcy = cy + dy * hs;
    float pw = expf(dw) * ws, ph = expf(dh) * hs;
    float bx1 = fminf(fmaxf(pcx - 0.5f * pw, 0.f), 640.f);
    float by1 = fminf(fmaxf(pcy - 0.5f * ph, 0.f), 640.f);
    float bx2 = fminf(fmaxf(pcx + 0.5f * pw, 0.f), 640.f);
    float by2 = fminf(fmaxf(pcy + 0.5f * ph, 0.f), 640.f);
    selBox[r] = make_float4(bx1, by1, bx2, by2);
}

// ---------------- greedy sequential NMS (single block) ----------------------
__global__ __launch_bounds__(1024)
void nms_k(const float4* __restrict__ boxes, const float* __restrict__ vals,
           unsigned char* __restrict__ keepOut)
{
    __shared__ float4 sb[KTOP];
    __shared__ float sarea[KTOP];
    __shared__ unsigned char sk[KTOP];
    int t = threadIdx.x;
    if (t < KTOP) {
        float4 b = boxes[t];
        sb[t] = b;
        sarea[t] = fmaxf(b.z - b.x, 0.f) * fmaxf(b.w - b.y, 0.f);
        sk[t] = (vals[t] > 0.f) ? 1 : 0;
    }
    __syncthreads();
    for (int i = 0; i < KTOP; i++) {
        if (sk[i]) {
            if (t > i && t < KTOP && sk[t]) {
                float4 bi = sb[i], bj = sb[t];
                float xx1 = fmaxf(bi.x, bj.x), yy1 = fmaxf(bi.y, bj.y);
                float xx2 = fminf(bi.z, bj.z), yy2 = fminf(bi.w, bj.w);
                float inter = fmaxf(xx2 - xx1, 0.f) * fmaxf(yy2 - yy1, 0.f);
                float iou = inter / (sarea[i] + sarea[t] - inter + 1e-8f);
                if (iou > 0.5f) sk[t] = 0;
            }
            __syncthreads();
        }
    }
    __syncthreads();
    if (t < KTOP) keepOut[t] = sk[t];
}

// ---------------- pack output: scores | classes | boxes | keep ---------------
__global__ void output_k(const float* __restrict__ vals, const int* __restrict__ cls,
                         const float4* __restrict__ boxes,
                         const unsigned char* __restrict__ keep,
                         float* __restrict__ out, int out_size)
{
    int r = blockIdx.x * blockDim.x + threadIdx.x;
    if (r >= KTOP) return;
    bool k = keep[r] != 0;
    float4 b = boxes[r];
    if (r < out_size) out[r] = k ? vals[r] : 0.f;
    if (1000 + r < out_size) out[1000 + r] = (float)cls[r];
    if (2000 + 4 * r + 3 < out_size) {
        out[2000 + 4 * r + 0] = k ? b.x : 0.f;
        out[2000 + 4 * r + 1] = k ? b.y : 0.f;
        out[2000 + 4 * r + 2] = k ? b.z : 0.f;
        out[2000 + 4 * r + 3] = k ? b.w : 0.f;
    }
    if (6000 + r < out_size) out[6000 + r] = k ? 1.f : 0.f;
}

// ---------------- host orchestration ----------------------------------------
extern "C" void kernel_launch(void* const* d_in, const int* in_sizes, int n_in,
                              void* d_out, int out_size)
{
    (void)in_sizes; (void)n_in;
    const float* f0 = (const float*)d_in[0];
    const float* f1 = (const float*)d_in[1];
    const float* f2 = (const float*)d_in[2];
    const float* f3 = (const float*)d_in[3];
    const float* f4 = (const float*)d_in[4];
    const float* cls_w  = (const float*)d_in[5];
    const float* cls_b  = (const float*)d_in[6];
    const float* cls_hw = (const float*)d_in[7];
    const float* cls_hb = (const float*)d_in[8];
    const float* reg_w  = (const float*)d_in[9];
    const float* reg_b  = (const float*)d_in[10];
    const float* reg_hw = (const float*)d_in[11];
    const float* reg_hb = (const float*)d_in[12];

    float *bufA, *bufB, *wTrk, *wCls, *wReg, *clsR, *regR, *scores, *topVal;
    int *arg, *selCls;
    float4 *loc, *selBox;
    ull* keys;
    unsigned char* keep;
    cudaGetSymbolAddress((void**)&bufA, g_bufA);
    cudaGetSymbolAddress((void**)&bufB, g_bufB);
    cudaGetSymbolAddress((void**)&wTrk, g_wTrunk);
    cudaGetSymbolAddress((void**)&wCls, g_wCls);
    cudaGetSymbolAddress((void**)&wReg, g_wReg);
    cudaGetSymbolAddress((void**)&clsR, g_cls);
    cudaGetSymbolAddress((void**)&regR, g_reg);
    cudaGetSymbolAddress((void**)&scores, g_scores);
    cudaGetSymbolAddress((void**)&arg, g_arg);
    cudaGetSymbolAddress((void**)&loc, g_loc);
    cudaGetSymbolAddress((void**)&keys, g_keys);
    cudaGetSymbolAddress((void**)&selBox, g_selBox);
    cudaGetSymbolAddress((void**)&topVal, g_topVal);
    cudaGetSymbolAddress((void**)&selCls, g_selCls);
    cudaGetSymbolAddress((void**)&keep, g_keep);

    // weight transposes (per call — weights are inputs)
    const int TRK = 4*256*9*256;
    transpose_trunk_k<<<CDIV(TRK,256), 256>>>(cls_w, wTrk);
    transpose_trunk_k<<<CDIV(TRK,256), 256>>>(reg_w, wTrk + TRK);
    transpose_head_k<<<CDIV(256*9*768,256), 256>>>(cls_hw, wCls, 720, 768);
    transpose_head_k<<<CDIV(256*9*128,256), 256>>>(reg_hw, wReg, 36, 128);

    // fused trunk layers over all 5 levels x 2 towers
    dim3 gt(139, 2, 2);
    conv_trunk_k<<<gt, 256>>>(f0,f1,f2,f3,f4, nullptr, bufA, wTrk, cls_b, reg_b, 0, 1);
    conv_trunk_k<<<gt, 256>>>(f0,f1,f2,f3,f4, bufA,    bufB, wTrk, cls_b, reg_b, 1, 0);
    conv_trunk_k<<<gt, 256>>>(f0,f1,f2,f3,f4, bufB,    bufA, wTrk, cls_b, reg_b, 2, 0);
    conv_trunk_k<<<gt, 256>>>(f0,f1,f2,f3,f4, bufA,    bufB, wTrk, cls_b, reg_b, 3, 0);
    // heads
    dim3 gh(139, 7, 1);
    conv_head_k<<<gh, 256>>>(bufB, clsR, regR, wCls, wReg, cls_hb, reg_hb);

    score_key_k<<<N_SORT / 256, 256>>>(clsR, regR, scores, arg, loc, keys);

    // sort: fused local sort (k=2..2048), then global merge phases
    bitonic_local_k<<<N_SORT / 2048, 1024>>>(keys);
    for (int k = 4096; k <= N_SORT; k <<= 1) {
        int j = k >> 1;
        for (; j > 1024; j >>= 1)
            bitonic_global_k<<<N_SORT / 256, 256>>>(keys, k, j);
        bitonic_shared_k<<<N_SORT / 2048, 1024>>>(keys, k, j);
    }

    decode_k<<<CDIV(KTOP, 256), 256>>>(keys, scores, arg, loc, selBox, topVal, selCls);
    nms_k<<<1, 1024>>>(selBox, topVal, keep);
    output_k<<<CDIV(KTOP, 256), 256>>>(topVal, selCls, selBox, keep,
                                       (float*)d_out, out_size);
}

// round 5
// speedup vs baseline: 3.2937x; 1.0537x over previous
#include <cuda_runtime.h>
#include <math.h>

#define CDIV(a,b) (((a)+(b)-1)/(b))
#define N_ANCH 76725
#define N_SORT 131072
#define KTOP   1000
#define TS     (256*8525)          // per-tower activation buffer stride (floats)
typedef unsigned long long ull;

// ---------------- scratch (static device globals; no allocation) -------------
__device__ float g_bufA[2*TS];                 // [tower][C=256][HW concat]
__device__ float g_bufB[2*TS];
__device__ float g_wTrunk[2*4*256*9*256];      // [tower][layer][ci][k][co]
__device__ float g_wCls[256*9*768];            // [ci][k][co(pad 768)]
__device__ float g_wReg[256*9*128];            // [ci][k][co(pad 128)]
__device__ float g_cls[720*8525];
__device__ float g_reg[36*8525];
__device__ float g_scores[N_ANCH];
__device__ int   g_arg[N_ANCH];
__device__ float4 g_loc[N_ANCH];
__device__ ull   g_keys[N_SORT];
__device__ ull   g_tmpA[32*1024];
__device__ ull   g_tmpB[16*1024];
__device__ unsigned g_mask[KTOP*32];
__device__ float4 g_selBox[KTOP];
__device__ float  g_topVal[KTOP];
__device__ int    g_selCls[KTOP];
__device__ unsigned char g_keep[KTOP];

// ---------------- weight transposes ------------------------------------------
__global__ void transpose_trunk_k(const float* __restrict__ src, float* __restrict__ dst)
{
    int idx = blockIdx.x * blockDim.x + threadIdx.x;
    if (idx >= 4*256*9*256) return;
    int co = idx & 255, r = idx >> 8;
    int kk = r % 9, r2 = r / 9;
    int ci = r2 & 255, layer = r2 >> 8;
    dst[idx] = src[((layer*256 + co)*256 + ci)*9 + kk];
}
__global__ void transpose_head_k(const float* __restrict__ src, float* __restrict__ dst,
                                 int Cout, int STR)
{
    int idx = blockIdx.x * blockDim.x + threadIdx.x;
    if (idx >= 256*9*STR) return;
    int co = idx % STR, r = idx / STR;
    int kk = r % 9, ci = r / 9;
    dst[idx] = (co < Cout) ? src[(co*256 + ci)*9 + kk] : 0.f;
}

// ---------------- packed fp32x2 helpers --------------------------------------
__device__ __forceinline__ void ffma2(ull& d, ull a, ull b) {
    asm("fma.rn.f32x2 %0, %1, %2, %0;" : "+l"(d) : "l"(a), "l"(b));
}
__device__ __forceinline__ ull pack2(float v) {
    ull r; asm("mov.b64 %0, {%1, %1};" : "=l"(r) : "f"(v)); return r;
}
__device__ __forceinline__ float lo32(ull a) { return __uint_as_float((unsigned)a); }
__device__ __forceinline__ float hi32(ull a) { return __uint_as_float((unsigned)(a >> 32)); }

// ---------------- tile/level decode ------------------------------------------
__device__ __forceinline__ void tile_decode(int t, int& L, int& H, int& hwBase,
                                            int& x0, int& y0)
{
    int tpr;
    if      (t < 100) { L=0; H=80; hwBase=0;    tpr=10; }
    else if (t < 125) { L=1; H=40; hwBase=6400; tpr=5;  t-=100; }
    else if (t < 134) { L=2; H=20; hwBase=8000; tpr=3;  t-=125; }
    else if (t < 138) { L=3; H=10; hwBase=8400; tpr=2;  t-=134; }
    else              { L=4; H=5;  hwBase=8500; tpr=1;  t-=138; }
    x0 = (t % tpr) * 8; y0 = (t / tpr) * 8;
}

// ---------------- conv core: 128co x 8x8px per block, FFMA2 ------------------
__device__ __forceinline__ void conv_core(
    const float* __restrict__ in, const float* __restrict__ wT, int STR,
    int coBase, const float* __restrict__ bias, float* __restrict__ out,
    int Cout, int relu, int H, int x0, int y0)
{
    const int W = H, HW = H * W;
    const int tid = threadIdx.x;
    const int p = tid & 15, q = tid >> 4;
    const int pyb = (p >> 2) * 2, pxb = (p & 3) * 2;
    const int coQ = q * 8;

    __shared__ __align__(16) float s_w[8*9*128];
    __shared__ __align__(16) ull s_in2[8*10*14];

    // hoisted fill geometry (4 items/thread, 800 total)
    int  sAddr[4]; int gInv[4]; bool okL[4], okS[4];
    #pragma unroll
    for (int j = 0; j < 4; j++) {
        int idx = tid + j * 256;
        int ci = idx / 100, r = idx % 100, dy = r / 10, dx = r % 10;
        int gy = y0 - 1 + dy, gx = x0 - 1 + dx;
        okS[j] = idx < 800;
        okL[j] = okS[j] && gy >= 0 && gy < H && gx >= 0 && gx < W;
        gInv[j] = okL[j] ? (ci * HW + gy * W + gx) : 0;
        sAddr[j] = ci * 140 + dy * 14 + dx;
    }
    const int co = tid & 127, half = tid >> 7;

    ull acc[2][2][4] = {};

    for (int cinBase = 0; cinBase < 256; cinBase += 8) {
        #pragma unroll
        for (int j = 0; j < 4; j++) {
            if (okS[j]) {
                float v = okL[j] ? __ldg(in + gInv[j] + cinBase * HW) : 0.f;
                s_in2[sAddr[j]] = pack2(v);
            }
        }
        {
            const float* wp = wT + (cinBase * 9 + half) * STR + coBase + co;
            float* sp = s_w + half * 128 + co;
            #pragma unroll
            for (int r = 0; r < 36; r++)
                sp[r * 256] = wp[r * 2 * STR];
        }
        __syncthreads();

        #pragma unroll 1
        for (int ci = 0; ci < 8; ci++) {
            const ull* rowb = s_in2 + ci * 140;
            const float* wcb = s_w + ci * 9 * 128 + coQ;
            // cache the 4 input rows this thread touches (LDS.128 pairs)
            ull iv[4][4];
            #pragma unroll
            for (int r = 0; r < 4; r++) {
                const ulonglong2* rp = (const ulonglong2*)(rowb + (pyb + r) * 14 + pxb);
                ulonglong2 v0 = rp[0], v1 = rp[1];
                iv[r][0] = v0.x; iv[r][1] = v0.y; iv[r][2] = v1.x; iv[r][3] = v1.y;
            }
            #pragma unroll
            for (int ky = 0; ky < 3; ky++) {
                #pragma unroll
                for (int kx = 0; kx < 3; kx++) {
                    const float* wrow = wcb + (ky * 3 + kx) * 128;
                    ulonglong2 wa = *(const ulonglong2*)(wrow);
                    ulonglong2 wb = *(const ulonglong2*)(wrow + 4);
                    #pragma unroll
                    for (int py = 0; py < 2; py++)
                        #pragma unroll
                        for (int px = 0; px < 2; px++) {
                            ull v = iv[ky + py][px + kx];
                            ffma2(acc[py][px][0], v, wa.x);
                            ffma2(acc[py][px][1], v, wa.y);
                            ffma2(acc[py][px][2], v, wb.x);
                            ffma2(acc[py][px][3], v, wb.y);
                        }
                }
            }
        }
        __syncthreads();
    }

    #pragma unroll
    for (int pr = 0; pr < 4; pr++) {
        int c0 = coBase + coQ + pr * 2, c1 = c0 + 1;
        if (c0 >= Cout) continue;
        float b0 = bias[c0];
        float b1 = (c1 < Cout) ? bias[c1] : 0.f;
        #pragma unroll
        for (int py = 0; py < 2; py++) {
            int y = y0 + pyb + py;
            if (y >= H) continue;
            #pragma unroll
            for (int px = 0; px < 2; px++) {
                int x = x0 + pxb + px;
                if (x >= W) continue;
                float v0 = lo32(acc[py][px][pr]) + b0;
                float v1 = hi32(acc[py][px][pr]) + b1;
                if (relu) { v0 = fmaxf(v0, 0.f); v1 = fmaxf(v1, 0.f); }
                out[c0 * HW + y * W + x] = v0;
                if (c1 < Cout) out[c1 * HW + y * W + x] = v1;
            }
        }
    }
}

__global__ __launch_bounds__(256, 2)
void conv_trunk_k(const float* f0, const float* f1, const float* f2,
                  const float* f3, const float* f4,
                  const float* __restrict__ actIn, float* __restrict__ actOut,
                  const float* __restrict__ wT,
                  const float* __restrict__ biasCls, const float* __restrict__ biasReg,
                  int layer, int isFirst)
{
    int L, H, hwBase, x0, y0;
    tile_decode(blockIdx.x, L, H, hwBase, x0, y0);
    const int tower = blockIdx.z;
    const int coBase = blockIdx.y * 128;
    const float* in;
    if (isFirst) {
        const float* fs[5] = {f0, f1, f2, f3, f4};
        in = fs[L];
    } else {
        in = actIn + tower * TS + hwBase * 256;
    }
    const float* w = wT + (tower * 4 + layer) * (256*9*256);
    const float* b = (tower ? biasReg : biasCls) + layer * 256;
    float* out = actOut + tower * TS + hwBase * 256;
    conv_core(in, w, 256, coBase, b, out, 256, 1, H, x0, y0);
}

__global__ __launch_bounds__(256, 2)
void conv_head_k(const float* __restrict__ actIn,
                 float* __restrict__ outCls, float* __restrict__ outReg,
                 const float* __restrict__ wTc, const float* __restrict__ wTr,
                 const float* __restrict__ biasC, const float* __restrict__ biasR)
{
    int L, H, hwBase, x0, y0;
    tile_decode(blockIdx.x, L, H, hwBase, x0, y0);
    const int yy = blockIdx.y;
    if (yy < 6) {
        const float* in = actIn + 0 * TS + hwBase * 256;
        conv_core(in, wTc, 768, yy * 128, biasC, outCls + 720 * hwBase, 720, 0, H, x0, y0);
    } else {
        const float* in = actIn + 1 * TS + hwBase * 256;
        conv_core(in, wTr, 128, 0, biasR, outReg + 36 * hwBase, 36, 0, H, x0, y0);
    }
}

// ---------------- scores/argmax/keys: class-major coalesced mapping ----------
__global__ void score_key_k(const float* __restrict__ cls_raw,
                            const float* __restrict__ reg_raw,
                            float* __restrict__ scores, int* __restrict__ arg,
                            float4* __restrict__ loc,
                            ull* __restrict__ keys)
{
    int t = blockIdx.x * blockDim.x + threadIdx.x;
    if (t >= N_SORT) return;
    if (t >= N_ANCH) { keys[t] = 0xFFFFFFFFFFFFFFFFULL; return; }

    // class-major order within each level: rel = a*HW + p  (coalesced in p)
    int L, a, p, HW, cum;
    if      (t < 57600) { L=0; int rel=t;       HW=6400; a=rel/6400; p=rel%6400; cum=0;    }
    else if (t < 72000) { L=1; int rel=t-57600; HW=1600; a=rel/1600; p=rel%1600; cum=6400; }
    else if (t < 75600) { L=2; int rel=t-72000; HW=400;  a=rel/400;  p=rel%400;  cum=8000; }
    else if (t < 76500) { L=3; int rel=t-75600; HW=100;  a=rel/100;  p=rel%100;  cum=8400; }
    else                { L=4; int rel=t-76500; HW=25;   a=rel/25;   p=rel%25;   cum=8500; }
    const int aoff[5] = {0, 57600, 72000, 75600, 76500};
    int idx = aoff[L] + p * 9 + a;

    // argmax over SIGMOID values (post-sigmoid saturation ties break by first idx)
    const float* cb = cls_raw + 720 * cum + (a * 80) * HW + p;
    float best = 1.f / (1.f + expf(-cb[0]));
    int barg = 0;
    for (int c = 1; c < 80; c++) {
        float s = 1.f / (1.f + expf(-cb[c * HW]));
        if (s > best) { best = s; barg = c; }
    }
    float masked = (best > 0.05f) ? best : -1.0f;
    scores[idx] = masked;
    arg[idx] = barg;

    const float* rb = reg_raw + 36 * cum + (a * 4) * HW + p;
    loc[idx] = make_float4(rb[0], rb[HW], rb[2 * HW], rb[3 * HW]);

    unsigned u = __float_as_uint(masked);
    u = (u & 0x80000000u) ? ~u : (u | 0x80000000u);
    keys[idx] = (((ull)(~u)) << 32) | (unsigned)idx;   // ascending = best first
}

// ---------------- local sort: 2048-chunks fully ascending --------------------
__global__ __launch_bounds__(1024)
void bitonic_local_k(ull* __restrict__ keys)
{
    __shared__ ull s[2048];
    int tid = threadIdx.x;
    int base = blockIdx.x * 2048;
    s[tid] = keys[base + tid];
    s[tid + 1024] = keys[base + tid + 1024];
    __syncthreads();
    for (int k = 2; k <= 2048; k <<= 1) {
        for (int j = k >> 1; j >= 1; j >>= 1) {
            #pragma unroll
            for (int h = 0; h < 2; h++) {
                int l = tid + h * 1024;
                int ixj = l ^ j;
                if (ixj > l) {
                    ull a = s[l], b = s[ixj];
                    bool up = ((l & k) == 0);   // local direction -> each chunk ascending
                    if ((a > b) == up) { s[l] = b; s[ixj] = a; }
                }
            }
            __syncthreads();
        }
    }
    keys[base + tid] = s[tid];
    keys[base + tid + 1024] = s[tid + 1024];
}

// ---------------- tournament merge: 2 sorted-1024 lists -> best 1024 ---------
__global__ __launch_bounds__(512)
void topk_merge_k(const ull* __restrict__ in, ull* __restrict__ out, int inStride)
{
    __shared__ ull s[2048];
    int t = threadIdx.x;
    const ull* A = in + (size_t)blockIdx.x * 2 * inStride;
    const ull* B = A + inStride;
    #pragma unroll
    for (int i = t; i < 1024; i += 512) {
        s[i] = A[i];
        s[2047 - i] = B[i];     // reversed -> bitonic sequence
    }
    __syncthreads();
    for (int j = 1024; j >= 1; j >>= 1) {
        #pragma unroll
        for (int h = 0; h < 4; h++) {
            int l = t + h * 512;
            int ixj = l ^ j;
            if (ixj > l) {
                ull a = s[l], b = s[ixj];
                if (a > b) { s[l] = b; s[ixj] = a; }
            }
        }
        __syncthreads();
    }
    #pragma unroll
    for (int i = t; i < 1024; i += 512)
        out[blockIdx.x * 1024 + i] = s[i];
}

// ---------------- decode top-1000 boxes --------------------------------------
__device__ __forceinline__ void anchor_split(int idx, int& L, int& p, int& a, int& Wd)
{
    const int aoff[6] = {0, 57600, 72000, 75600, 76500, 76725};
    const int Ws[5] = {80, 40, 20, 10, 5};
    L = 0;
    while (L < 4 && idx >= aoff[L + 1]) L++;
    int rel = idx - aoff[L];
    p = rel / 9; a = rel - p * 9; Wd = Ws[L];
}

__global__ void decode_k(const ull* __restrict__ keys,
                         const float* __restrict__ scores,
                         const int* __restrict__ arg,
                         const float4* __restrict__ loc,
                         float4* __restrict__ selBox, float* __restrict__ topVal,
                         int* __restrict__ selCls)
{
    int r = blockIdx.x * blockDim.x + threadIdx.x;
    if (r >= KTOP) return;
    int idx = (int)(keys[r] & 0xFFFFFFFFULL);
    float val = scores[idx];
    topVal[r] = val;
    selCls[r] = arg[idx];

    const int strides[5] = {8, 16, 32, 64, 128};
    const int sizes[5] = {32, 64, 128, 256, 512};
    int L, p, a, W;
    anchor_split(idx, L, p, a, W);
    int y = p / W, x = p - y * W;
    int ri = a / 3, si = a - ri * 3;
    const float ratios[3] = {0.5f, 1.0f, 2.0f};
    const float scales[3] = {1.0f, 1.2599210498948732f, 1.5874010519681994f};
    float sq = sqrtf(ratios[ri]);
    float ws = (float)sizes[L] * scales[si] / sq;
    float hs = (float)sizes[L] * scales[si] * sq;
    float st = (float)strides[L];
    float cx = ((float)x + 0.5f) * st;
    float cy = ((float)y + 0.5f) * st;

    float4 l = loc[idx];
    float dx = l.x * 0.1f, dy = l.y * 0.1f, dw = l.z * 0.2f, dh = l.w * 0.2f;
    float pcx = cx + dx * ws, pcy = cy + dy * hs;
    float pw = expf(dw) * ws, ph = expf(dh) * hs;
    float bx1 = fminf(fmaxf(pcx - 0.5f * pw, 0.f), 640.f);
    float by1 = fminf(fmaxf(pcy - 0.5f * ph, 0.f), 640.f);
    float bx2 = fminf(fmaxf(pcx + 0.5f * pw, 0.f), 640.f);
    float by2 = fminf(fmaxf(pcy + 0.5f * ph, 0.f), 640.f);
    selBox[r] = make_float4(bx1, by1, bx2, by2);
}

// ---------------- NMS: parallel IoU bitmask + 1-warp sequential pass ---------
__global__ __launch_bounds__(1024)
void iou_mask_k(const float4* __restrict__ boxes, unsigned* __restrict__ mask)
{
    int i = blockIdx.x;
    int j = threadIdx.x;
    float4 bi = boxes[i];
    float4 bj = (j < KTOP) ? boxes[j] : make_float4(0,0,0,0);
    float ai = fmaxf(bi.z - bi.x, 0.f) * fmaxf(bi.w - bi.y, 0.f);
    float aj = fmaxf(bj.z - bj.x, 0.f) * fmaxf(bj.w - bj.y, 0.f);
    float xx1 = fmaxf(bi.x, bj.x), yy1 = fmaxf(bi.y, bj.y);
    float xx2 = fminf(bi.z, bj.z), yy2 = fminf(bi.w, bj.w);
    float inter = fmaxf(xx2 - xx1, 0.f) * fmaxf(yy2 - yy1, 0.f);
    float iou = inter / (ai + aj - inter + 1e-8f);
    bool sup = (j < KTOP) && (j > i) && (iou > 0.5f);
    unsigned bal = __ballot_sync(0xffffffffu, sup);
    if ((j & 31) == 0) mask[i * 32 + (j >> 5)] = bal;
}

__global__ void nms_seq_k(const unsigned* __restrict__ mask,
                          const float* __restrict__ vals,
                          unsigned char* __restrict__ keepOut)
{
    int lane = threadIdx.x;   // 32 threads; lane owns bits [32*lane .. 32*lane+31]
    unsigned validw = 0;
    #pragma unroll
    for (int b = 0; b < 32; b++) {
        int j = lane * 32 + b;
        if (j < KTOP && vals[j] > 0.f) validw |= (1u << b);
    }
    unsigned remv = 0;
    for (int i = 0; i < KTOP; i++) {
        unsigned row = mask[i * 32 + lane];           // prefetch (independent)
        unsigned rm = __shfl_sync(0xffffffffu, remv, i >> 5);
        unsigned vw = __shfl_sync(0xffffffffu, validw, i >> 5);
        unsigned bi = i & 31;
        if (((vw >> bi) & 1) && !((rm >> bi) & 1))
            remv |= row;
    }
    #pragma unroll
    for (int b = 0; b < 32; b++) {
        int j = lane * 32 + b;
        if (j < KTOP)
            keepOut[j] = (unsigned char)(((validw >> b) & 1) && !((remv >> b) & 1));
    }
}

// ---------------- pack output: scores | classes | boxes | keep ---------------
__global__ void output_k(const float* __restrict__ vals, const int* __restrict__ cls,
                         const float4* __restrict__ boxes,
                         const unsigned char* __restrict__ keep,
                         float* __restrict__ out, int out_size)
{
    int r = blockIdx.x * blockDim.x + threadIdx.x;
    if (r >= KTOP) return;
    bool k = keep[r] != 0;
    float4 b = boxes[r];
    if (r < out_size) out[r] = k ? vals[r] : 0.f;
    if (1000 + r < out_size) out[1000 + r] = (float)cls[r];
    if (2000 + 4 * r + 3 < out_size) {
        out[2000 + 4 * r + 0] = k ? b.x : 0.f;
        out[2000 + 4 * r + 1] = k ? b.y : 0.f;
        out[2000 + 4 * r + 2] = k ? b.z : 0.f;
        out[2000 + 4 * r + 3] = k ? b.w : 0.f;
    }
    if (6000 + r < out_size) out[6000 + r] = k ? 1.f : 0.f;
}

// ---------------- host orchestration ----------------------------------------
extern "C" void kernel_launch(void* const* d_in, const int* in_sizes, int n_in,
                              void* d_out, int out_size)
{
    (void)in_sizes; (void)n_in;
    const float* f0 = (const float*)d_in[0];
    const float* f1 = (const float*)d_in[1];
    const float* f2 = (const float*)d_in[2];
    const float* f3 = (const float*)d_in[3];
    const float* f4 = (const float*)d_in[4];
    const float* cls_w  = (const float*)d_in[5];
    const float* cls_b  = (const float*)d_in[6];
    const float* cls_hw = (const float*)d_in[7];
    const float* cls_hb = (const float*)d_in[8];
    const float* reg_w  = (const float*)d_in[9];
    const float* reg_b  = (const float*)d_in[10];
    const float* reg_hw = (const float*)d_in[11];
    const float* reg_hb = (const float*)d_in[12];

    float *bufA, *bufB, *wTrk, *wCls, *wReg, *clsR, *regR, *scores, *topVal;
    int *arg, *selCls;
    float4 *loc, *selBox;
    ull *keys, *tmpA, *tmpB;
    unsigned *mask;
    unsigned char* keep;
    cudaGetSymbolAddress((void**)&bufA, g_bufA);
    cudaGetSymbolAddress((void**)&bufB, g_bufB);
    cudaGetSymbolAddress((void**)&wTrk, g_wTrunk);
    cudaGetSymbolAddress((void**)&wCls, g_wCls);
    cudaGetSymbolAddress((void**)&wReg, g_wReg);
    cudaGetSymbolAddress((void**)&clsR, g_cls);
    cudaGetSymbolAddress((void**)&regR, g_reg);
    cudaGetSymbolAddress((void**)&scores, g_scores);
    cudaGetSymbolAddress((void**)&arg, g_arg);
    cudaGetSymbolAddress((void**)&loc, g_loc);
    cudaGetSymbolAddress((void**)&keys, g_keys);
    cudaGetSymbolAddress((void**)&tmpA, g_tmpA);
    cudaGetSymbolAddress((void**)&tmpB, g_tmpB);
    cudaGetSymbolAddress((void**)&mask, g_mask);
    cudaGetSymbolAddress((void**)&selBox, g_selBox);
    cudaGetSymbolAddress((void**)&topVal, g_topVal);
    cudaGetSymbolAddress((void**)&selCls, g_selCls);
    cudaGetSymbolAddress((void**)&keep, g_keep);

    const int TRK = 4*256*9*256;
    transpose_trunk_k<<<CDIV(TRK,256), 256>>>(cls_w, wTrk);
    transpose_trunk_k<<<CDIV(TRK,256), 256>>>(reg_w, wTrk + TRK);
    transpose_head_k<<<CDIV(256*9*768,256), 256>>>(cls_hw, wCls, 720, 768);
    transpose_head_k<<<CDIV(256*9*128,256), 256>>>(reg_hw, wReg, 36, 128);

    dim3 gt(139, 2, 2);
    conv_trunk_k<<<gt, 256>>>(f0,f1,f2,f3,f4, nullptr, bufA, wTrk, cls_b, reg_b, 0, 1);
    conv_trunk_k<<<gt, 256>>>(f0,f1,f2,f3,f4, bufA,    bufB, wTrk, cls_b, reg_b, 1, 0);
    conv_trunk_k<<<gt, 256>>>(f0,f1,f2,f3,f4, bufB,    bufA, wTrk, cls_b, reg_b, 2, 0);
    conv_trunk_k<<<gt, 256>>>(f0,f1,f2,f3,f4, bufA,    bufB, wTrk, cls_b, reg_b, 3, 0);
    dim3 gh(139, 7, 1);
    conv_head_k<<<gh, 256>>>(bufB, clsR, regR, wCls, wReg, cls_hb, reg_hb);

    score_key_k<<<N_SORT / 256, 256>>>(clsR, regR, scores, arg, loc, keys);

    // top-1024 tournament: local sort 64 chunks, then 6 merge-and-prune rounds
    bitonic_local_k<<<N_SORT / 2048, 1024>>>(keys);
    topk_merge_k<<<32, 512>>>(keys, tmpA, 2048);   // 64 -> 32 lists
    topk_merge_k<<<16, 512>>>(tmpA, tmpB, 1024);   // 32 -> 16
    topk_merge_k<<< 8, 512>>>(tmpB, tmpA, 1024);   // 16 -> 8
    topk_merge_k<<< 4, 512>>>(tmpA, tmpB, 1024);   //  8 -> 4
    topk_merge_k<<< 2, 512>>>(tmpB, tmpA, 1024);   //  4 -> 2
    topk_merge_k<<< 1, 512>>>(tmpA, tmpB, 1024);   //  2 -> 1 (final in tmpB)

    decode_k<<<CDIV(KTOP, 256), 256>>>(tmpB, scores, arg, loc, selBox, topVal, selCls);
    iou_mask_k<<<KTOP, 1024>>>(selBox, mask);
    nms_seq_k<<<1, 32>>>(mask, topVal, keep);
    output_k<<<CDIV(KTOP, 256), 256>>>(topVal, selCls, selBox, keep,
                                       (float*)d_out, out_size);
}

// round 6
// speedup vs baseline: 3.8384x; 1.1654x over previous
#include <cuda_runtime.h>
#include <math.h>

#define CDIV(a,b) (((a)+(b)-1)/(b))
#define N_ANCH 76725
#define N_SORT 131072
#define KTOP   1000
#define TS     (256*8525)
typedef unsigned long long ull;

// dynamic smem layout: wBuf[2][9216] floats, then inBuf[2][1120] ull
#define WBUF_FLOATS 9216
#define INBUF_ULLS  1120
#define DYN_SMEM (2*WBUF_FLOATS*4 + 2*INBUF_ULLS*8)

// ---------------- scratch (static device globals; no allocation) -------------
__device__ float g_bufA[2*TS];
__device__ float g_bufB[2*TS];
__device__ float g_wTrunk[2*4*256*9*256];      // [tower][layer][ci][k][co]
__device__ float g_wCls[256*9*768];
__device__ float g_wReg[256*9*128];
__device__ float g_cls[720*8525];
__device__ float g_reg[36*8525];
__device__ float g_scores[N_ANCH];
__device__ int   g_arg[N_ANCH];
__device__ float4 g_loc[N_ANCH];
__device__ ull   g_keys[N_SORT];
__device__ ull   g_tmpA[32*1024];
__device__ ull   g_tmpB[16*1024];
__device__ unsigned g_mask[KTOP*32];
__device__ float4 g_selBox[KTOP];
__device__ float  g_topVal[KTOP];
__device__ int    g_selCls[KTOP];
__device__ unsigned char g_keep[KTOP];

// ---------------- weight transposes ------------------------------------------
__global__ void transpose_trunk_k(const float* __restrict__ src, float* __restrict__ dst)
{
    int idx = blockIdx.x * blockDim.x + threadIdx.x;
    if (idx >= 4*256*9*256) return;
    int co = idx & 255, r = idx >> 8;
    int kk = r % 9, r2 = r / 9;
    int ci = r2 & 255, layer = r2 >> 8;
    dst[idx] = src[((layer*256 + co)*256 + ci)*9 + kk];
}
__global__ void transpose_head_k(const float* __restrict__ src, float* __restrict__ dst,
                                 int Cout, int STR)
{
    int idx = blockIdx.x * blockDim.x + threadIdx.x;
    if (idx >= 256*9*STR) return;
    int co = idx % STR, r = idx / STR;
    int kk = r % 9, ci = r / 9;
    dst[idx] = (co < Cout) ? src[(co*256 + ci)*9 + kk] : 0.f;
}

// ---------------- helpers ----------------------------------------------------
__device__ __forceinline__ void ffma2(ull& d, ull a, ull b) {
    asm("fma.rn.f32x2 %0, %1, %2, %0;" : "+l"(d) : "l"(a), "l"(b));
}
__device__ __forceinline__ ull pack2(float v) {
    ull r; asm("mov.b64 %0, {%1, %1};" : "=l"(r) : "f"(v)); return r;
}
__device__ __forceinline__ float lo32(ull a) { return __uint_as_float((unsigned)a); }
__device__ __forceinline__ float hi32(ull a) { return __uint_as_float((unsigned)(a >> 32)); }
__device__ __forceinline__ void cp_async16(unsigned saddr, const void* gptr) {
    asm volatile("cp.async.cg.shared.global [%0], [%1], 16;" :: "r"(saddr), "l"(gptr));
}
#define CP_COMMIT() asm volatile("cp.async.commit_group;")
#define CP_WAIT0()  asm volatile("cp.async.wait_group 0;")

__device__ __forceinline__ void tile_decode(int t, int& L, int& H, int& hwBase,
                                            int& x0, int& y0)
{
    int tpr;
    if      (t < 100) { L=0; H=80; hwBase=0;    tpr=10; }
    else if (t < 125) { L=1; H=40; hwBase=6400; tpr=5;  t-=100; }
    else if (t < 134) { L=2; H=20; hwBase=8000; tpr=3;  t-=125; }
    else if (t < 138) { L=3; H=10; hwBase=8400; tpr=2;  t-=134; }
    else              { L=4; H=5;  hwBase=8500; tpr=1;  t-=138; }
    x0 = (t % tpr) * 8; y0 = (t / tpr) * 8;
}

// ---------------- conv core: pipelined, double-buffered ----------------------
__device__ __forceinline__ void conv_core(
    const float* __restrict__ in, const float* __restrict__ wT, int STR,
    int coBase, const float* __restrict__ bias, float* __restrict__ out,
    int Cout, int relu, int H, int x0, int y0)
{
    extern __shared__ __align__(16) char dynsmem[];
    float* wBuf = (float*)dynsmem;                              // [2][9216]
    ull*   inBuf = (ull*)(dynsmem + 2*WBUF_FLOATS*4);           // [2][1120]

    const int W = H, HW = H * W;
    const int tid = threadIdx.x;
    const int p = tid & 15, q = tid >> 4;
    const int pyb = (p >> 2) * 2, pxb = (p & 3) * 2;
    const int coQ = q * 8;

    // input-tile geometry (4 items/thread, 800 total)
    int  sAddr[4]; int gInv[4]; bool okL[4], okS[4];
    #pragma unroll
    for (int j = 0; j < 4; j++) {
        int idx = tid + j * 256;
        int ci = idx / 100, r = idx % 100, dy = r / 10, dx = r % 10;
        int gy = y0 - 1 + dy, gx = x0 - 1 + dx;
        okS[j] = idx < 800;
        okL[j] = okS[j] && gy >= 0 && gy < H && gx >= 0 && gx < W;
        gInv[j] = okL[j] ? (ci * HW + gy * W + gx) : 0;
        sAddr[j] = ci * 140 + dy * 14 + dx;
    }

    // weight fill: 2304 16B-chunks, 9 per thread (recomputed, no reg cache)
    auto issueW = [&](int chunk, int bIdx) {
        const float* wp = wT + chunk * 72 * STR + coBase;
        unsigned sb = (unsigned)__cvta_generic_to_shared(wBuf + bIdx * WBUF_FLOATS);
        #pragma unroll
        for (int c = 0; c < 9; c++) {
            int i = tid + c * 256;
            int row = i >> 5, lane = i & 31;
            cp_async16(sb + row * 512 + lane * 16, wp + row * STR + lane * 4);
        }
        CP_COMMIT();
    };
    auto loadIn = [&](int chunk, float vreg[4]) {
        #pragma unroll
        for (int j = 0; j < 4; j++)
            vreg[j] = okL[j] ? __ldg(in + gInv[j] + chunk * 8 * HW) : 0.f;
    };
    auto storeIn = [&](int bIdx, const float vreg[4]) {
        #pragma unroll
        for (int j = 0; j < 4; j++)
            if (okS[j]) inBuf[bIdx * INBUF_ULLS + sAddr[j]] = pack2(vreg[j]);
    };

    // prologue: chunk 0 into buffer 0
    {
        float v0[4];
        issueW(0, 0);
        loadIn(0, v0);
        storeIn(0, v0);
        CP_WAIT0();
    }
    __syncthreads();

    ull acc[2][2][4] = {};

    #pragma unroll 1
    for (int chunk = 0; chunk < 32; chunk++) {
        const int cur = chunk & 1;
        const bool more = (chunk + 1) < 32;
        float vnext[4];
        if (more) { issueW(chunk + 1, cur ^ 1); loadIn(chunk + 1, vnext); }

        const float* s_w = wBuf + cur * WBUF_FLOATS;
        const ull* s_base = inBuf + cur * INBUF_ULLS;

        #pragma unroll 1
        for (int ci = 0; ci < 8; ci++) {
            const ull* rowb = s_base + ci * 140;
            const float* wcb = s_w + ci * 9 * 128 + coQ;
            ull iv[4][4];
            #pragma unroll
            for (int r = 0; r < 4; r++) {
                const ulonglong2* rp = (const ulonglong2*)(rowb + (pyb + r) * 14 + pxb);
                ulonglong2 v0 = rp[0], v1 = rp[1];
                iv[r][0] = v0.x; iv[r][1] = v0.y; iv[r][2] = v1.x; iv[r][3] = v1.y;
            }
            #pragma unroll
            for (int ky = 0; ky < 3; ky++) {
                #pragma unroll
                for (int kx = 0; kx < 3; kx++) {
                    const float* wrow = wcb + (ky * 3 + kx) * 128;
                    ulonglong2 wa = *(const ulonglong2*)(wrow);
                    ulonglong2 wb = *(const ulonglong2*)(wrow + 4);
                    #pragma unroll
                    for (int py = 0; py < 2; py++)
                        #pragma unroll
                        for (int px = 0; px < 2; px++) {
                            ull v = iv[ky + py][px + kx];
                            ffma2(acc[py][px][0], v, wa.x);
                            ffma2(acc[py][px][1], v, wa.y);
                            ffma2(acc[py][px][2], v, wb.x);
                            ffma2(acc[py][px][3], v, wb.y);
                        }
                }
            }
        }

        if (more) { storeIn(cur ^ 1, vnext); CP_WAIT0(); }
        __syncthreads();
    }

    #pragma unroll
    for (int pr = 0; pr < 4; pr++) {
        int c0 = coBase + coQ + pr * 2, c1 = c0 + 1;
        if (c0 >= Cout) continue;
        float b0 = bias[c0];
        float b1 = (c1 < Cout) ? bias[c1] : 0.f;
        #pragma unroll
        for (int py = 0; py < 2; py++) {
            int y = y0 + pyb + py;
            if (y >= H) continue;
            #pragma unroll
            for (int px = 0; px < 2; px++) {
                int x = x0 + pxb + px;
                if (x >= W) continue;
                float v0 = lo32(acc[py][px][pr]) + b0;
                float v1 = hi32(acc[py][px][pr]) + b1;
                if (relu) { v0 = fmaxf(v0, 0.f); v1 = fmaxf(v1, 0.f); }
                out[c0 * HW + y * W + x] = v0;
                if (c1 < Cout) out[c1 * HW + y * W + x] = v1;
            }
        }
    }
}

__global__ __launch_bounds__(256, 2)
void conv_trunk_k(const float* f0, const float* f1, const float* f2,
                  const float* f3, const float* f4,
                  const float* __restrict__ actIn, float* __restrict__ actOut,
                  const float* __restrict__ wT,
                  const float* __restrict__ biasCls, const float* __restrict__ biasReg,
                  int layer, int isFirst)
{
    int L, H, hwBase, x0, y0;
    tile_decode(blockIdx.x, L, H, hwBase, x0, y0);
    const int tower = blockIdx.z;
    const int coBase = blockIdx.y * 128;
    const float* in;
    if (isFirst) {
        const float* fs[5] = {f0, f1, f2, f3, f4};
        in = fs[L];
    } else {
        in = actIn + tower * TS + hwBase * 256;
    }
    const float* w = wT + (tower * 4 + layer) * (256*9*256);
    const float* b = (tower ? biasReg : biasCls) + layer * 256;
    float* out = actOut + tower * TS + hwBase * 256;
    conv_core(in, w, 256, coBase, b, out, 256, 1, H, x0, y0);
}

__global__ __launch_bounds__(256, 2)
void conv_head_k(const float* __restrict__ actIn,
                 float* __restrict__ outCls, float* __restrict__ outReg,
                 const float* __restrict__ wTc, const float* __restrict__ wTr,
                 const float* __restrict__ biasC, const float* __restrict__ biasR)
{
    int L, H, hwBase, x0, y0;
    tile_decode(blockIdx.x, L, H, hwBase, x0, y0);
    const int yy = blockIdx.y;
    if (yy < 6) {
        const float* in = actIn + 0 * TS + hwBase * 256;
        conv_core(in, wTc, 768, yy * 128, biasC, outCls + 720 * hwBase, 720, 0, H, x0, y0);
    } else {
        const float* in = actIn + 1 * TS + hwBase * 256;
        conv_core(in, wTr, 128, 0, biasR, outReg + 36 * hwBase, 36, 0, H, x0, y0);
    }
}

// ---------------- scores/argmax/keys -----------------------------------------
__global__ void score_key_k(const float* __restrict__ cls_raw,
                            const float* __restrict__ reg_raw,
                            float* __restrict__ scores, int* __restrict__ arg,
                            float4* __restrict__ loc,
                            ull* __restrict__ keys)
{
    int t = blockIdx.x * blockDim.x + threadIdx.x;
    if (t >= N_SORT) return;
    if (t >= N_ANCH) { keys[t] = 0xFFFFFFFFFFFFFFFFULL; return; }

    int L, a, p, HW, cum;
    if      (t < 57600) { L=0; int rel=t;       HW=6400; a=rel/6400; p=rel%6400; cum=0;    }
    else if (t < 72000) { L=1; int rel=t-57600; HW=1600; a=rel/1600; p=rel%1600; cum=6400; }
    else if (t < 75600) { L=2; int rel=t-72000; HW=400;  a=rel/400;  p=rel%400;  cum=8000; }
    else if (t < 76500) { L=3; int rel=t-75600; HW=100;  a=rel/100;  p=rel%100;  cum=8400; }
    else                { L=4; int rel=t-76500; HW=25;   a=rel/25;   p=rel%25;   cum=8500; }
    const int aoff[5] = {0, 57600, 72000, 75600, 76500};
    int idx = aoff[L] + p * 9 + a;

    const float* cb = cls_raw + 720 * cum + (a * 80) * HW + p;
    float best = 1.f / (1.f + expf(-cb[0]));
    int barg = 0;
    for (int c = 1; c < 80; c++) {
        float s = 1.f / (1.f + expf(-cb[c * HW]));
        if (s > best) { best = s; barg = c; }
    }
    float masked = (best > 0.05f) ? best : -1.0f;
    scores[idx] = masked;
    arg[idx] = barg;

    const float* rb = reg_raw + 36 * cum + (a * 4) * HW + p;
    loc[idx] = make_float4(rb[0], rb[HW], rb[2 * HW], rb[3 * HW]);

    unsigned u = __float_as_uint(masked);
    u = (u & 0x80000000u) ? ~u : (u | 0x80000000u);
    keys[idx] = (((ull)(~u)) << 32) | (unsigned)idx;
}

// ---------------- local sort + tournament top-K ------------------------------
__global__ __launch_bounds__(1024)
void bitonic_local_k(ull* __restrict__ keys)
{
    __shared__ ull s[2048];
    int tid = threadIdx.x;
    int base = blockIdx.x * 2048;
    s[tid] = keys[base + tid];
    s[tid + 1024] = keys[base + tid + 1024];
    __syncthreads();
    for (int k = 2; k <= 2048; k <<= 1) {
        for (int j = k >> 1; j >= 1; j >>= 1) {
            #pragma unroll
            for (int h = 0; h < 2; h++) {
                int l = tid + h * 1024;
                int ixj = l ^ j;
                if (ixj > l) {
                    ull a = s[l], b = s[ixj];
                    bool up = ((l & k) == 0);
                    if ((a > b) == up) { s[l] = b; s[ixj] = a; }
                }
            }
            __syncthreads();
        }
    }
    keys[base + tid] = s[tid];
    keys[base + tid + 1024] = s[tid + 1024];
}

__global__ __launch_bounds__(512)
void topk_merge_k(const ull* __restrict__ in, ull* __restrict__ out, int inStride)
{
    __shared__ ull s[2048];
    int t = threadIdx.x;
    const ull* A = in + (size_t)blockIdx.x * 2 * inStride;
    const ull* B = A + inStride;
    #pragma unroll
    for (int i = t; i < 1024; i += 512) {
        s[i] = A[i];
        s[2047 - i] = B[i];
    }
    __syncthreads();
    for (int j = 1024; j >= 1; j >>= 1) {
        #pragma unroll
        for (int h = 0; h < 4; h++) {
            int l = t + h * 512;
            int ixj = l ^ j;
            if (ixj > l) {
                ull a = s[l], b = s[ixj];
                if (a > b) { s[l] = b; s[ixj] = a; }
            }
        }
        __syncthreads();
    }
    #pragma unroll
    for (int i = t; i < 1024; i += 512)
        out[blockIdx.x * 1024 + i] = s[i];
}

// ---------------- decode top-1000 boxes --------------------------------------
__device__ __forceinline__ void anchor_split(int idx, int& L, int& p, int& a, int& Wd)
{
    const int aoff[6] = {0, 57600, 72000, 75600, 76500, 76725};
    const int Ws[5] = {80, 40, 20, 10, 5};
    L = 0;
    while (L < 4 && idx >= aoff[L + 1]) L++;
    int rel = idx - aoff[L];
    p = rel / 9; a = rel - p * 9; Wd = Ws[L];
}

__global__ void decode_k(const ull* __restrict__ keys,
                         const float* __restrict__ scores,
                         const int* __restrict__ arg,
                         const float4* __restrict__ loc,
                         float4* __restrict__ selBox, float* __restrict__ topVal,
                         int* __restrict__ selCls)
{
    int r = blockIdx.x * blockDim.x + threadIdx.x;
    if (r >= KTOP) return;
    int idx = (int)(keys[r] & 0xFFFFFFFFULL);
    float val = scores[idx];
    topVal[r] = val;
    selCls[r] = arg[idx];

    const int strides[5] = {8, 16, 32, 64, 128};
    const int sizes[5] = {32, 64, 128, 256, 512};
    int L, p, a, W;
    anchor_split(idx, L, p, a, W);
    int y = p / W, x = p - y * W;
    int ri = a / 3, si = a - ri * 3;
    const float ratios[3] = {0.5f, 1.0f, 2.0f};
    const float scales[3] = {1.0f, 1.2599210498948732f, 1.5874010519681994f};
    float sq = sqrtf(ratios[ri]);
    float ws = (float)sizes[L] * scales[si] / sq;
    float hs = (float)sizes[L] * scales[si] * sq;
    float st = (float)strides[L];
    float cx = ((float)x + 0.5f) * st;
    float cy = ((float)y + 0.5f) * st;

    float4 l = loc[idx];
    float dx = l.x * 0.1f, dy = l.y * 0.1f, dw = l.z * 0.2f, dh = l.w * 0.2f;
    float pcx = cx + dx * ws, pcy = cy + dy * hs;
    float pw = expf(dw) * ws, ph = expf(dh) * hs;
    float bx1 = fminf(fmaxf(pcx - 0.5f * pw, 0.f), 640.f);
    float by1 = fminf(fmaxf(pcy - 0.5f * ph, 0.f), 640.f);
    float bx2 = fminf(fmaxf(pcx + 0.5f * pw, 0.f), 640.f);
    float by2 = fminf(fmaxf(pcy + 0.5f * ph, 0.f), 640.f);
    selBox[r] = make_float4(bx1, by1, bx2, by2);
}

// ---------------- NMS --------------------------------------------------------
__global__ __launch_bounds__(1024)
void iou_mask_k(const float4* __restrict__ boxes, unsigned* __restrict__ mask)
{
    int i = blockIdx.x;
    int j = threadIdx.x;
    float4 bi = boxes[i];
    float4 bj = (j < KTOP) ? boxes[j] : make_float4(0,0,0,0);
    float ai = fmaxf(bi.z - bi.x, 0.f) * fmaxf(bi.w - bi.y, 0.f);
    float aj = fmaxf(bj.z - bj.x, 0.f) * fmaxf(bj.w - bj.y, 0.f);
    float xx1 = fmaxf(bi.x, bj.x), yy1 = fmaxf(bi.y, bj.y);
    float xx2 = fminf(bi.z, bj.z), yy2 = fminf(bi.w, bj.w);
    float inter = fmaxf(xx2 - xx1, 0.f) * fmaxf(yy2 - yy1, 0.f);
    float iou = inter / (ai + aj - inter + 1e-8f);
    bool sup = (j < KTOP) && (j > i) && (iou > 0.5f);
    unsigned bal = __ballot_sync(0xffffffffu, sup);
    if ((j & 31) == 0) mask[i * 32 + (j >> 5)] = bal;
}

__global__ void nms_seq_k(const unsigned* __restrict__ mask,
                          const float* __restrict__ vals,
                          unsigned char* __restrict__ keepOut)
{
    int lane = threadIdx.x;
    unsigned validw = 0;
    #pragma unroll
    for (int b = 0; b < 32; b++) {
        int j = lane * 32 + b;
        if (j < KTOP && vals[j] > 0.f) validw |= (1u << b);
    }
    unsigned remv = 0;
    for (int i = 0; i < KTOP; i++) {
        unsigned row = mask[i * 32 + lane];
        unsigned rm = __shfl_sync(0xffffffffu, remv, i >> 5);
        unsigned vw = __shfl_sync(0xffffffffu, validw, i >> 5);
        unsigned bi = i & 31;
        if (((vw >> bi) & 1) && !((rm >> bi) & 1))
            remv |= row;
    }
    #pragma unroll
    for (int b = 0; b < 32; b++) {
        int j = lane * 32 + b;
        if (j < KTOP)
            keepOut[j] = (unsigned char)(((validw >> b) & 1) && !((remv >> b) & 1));
    }
}

// ---------------- pack output ------------------------------------------------
__global__ void output_k(const float* __restrict__ vals, const int* __restrict__ cls,
                         const float4* __restrict__ boxes,
                         const unsigned char* __restrict__ keep,
                         float* __restrict__ out, int out_size)
{
    int r = blockIdx.x * blockDim.x + threadIdx.x;
    if (r >= KTOP) return;
    bool k = keep[r] != 0;
    float4 b = boxes[r];
    if (r < out_size) out[r] = k ? vals[r] : 0.f;
    if (1000 + r < out_size) out[1000 + r] = (float)cls[r];
    if (2000 + 4 * r + 3 < out_size) {
        out[2000 + 4 * r + 0] = k ? b.x : 0.f;
        out[2000 + 4 * r + 1] = k ? b.y : 0.f;
        out[2000 + 4 * r + 2] = k ? b.z : 0.f;
        out[2000 + 4 * r + 3] = k ? b.w : 0.f;
    }
    if (6000 + r < out_size) out[6000 + r] = k ? 1.f : 0.f;
}

// ---------------- host orchestration -----------------------------------------
extern "C" void kernel_launch(void* const* d_in, const int* in_sizes, int n_in,
                              void* d_out, int out_size)
{
    (void)in_sizes; (void)n_in;
    const float* f0 = (const float*)d_in[0];
    const float* f1 = (const float*)d_in[1];
    const float* f2 = (const float*)d_in[2];
    const float* f3 = (const float*)d_in[3];
    const float* f4 = (const float*)d_in[4];
    const float* cls_w  = (const float*)d_in[5];
    const float* cls_b  = (const float*)d_in[6];
    const float* cls_hw = (const float*)d_in[7];
    const float* cls_hb = (const float*)d_in[8];
    const float* reg_w  = (const float*)d_in[9];
    const float* reg_b  = (const float*)d_in[10];
    const float* reg_hw = (const float*)d_in[11];
    const float* reg_hb = (const float*)d_in[12];

    float *bufA, *bufB, *wTrk, *wCls, *wReg, *clsR, *regR, *scores, *topVal;
    int *arg, *selCls;
    float4 *loc, *selBox;
    ull *keys, *tmpA, *tmpB;
    unsigned *mask;
    unsigned char* keep;
    cudaGetSymbolAddress((void**)&bufA, g_bufA);
    cudaGetSymbolAddress((void**)&bufB, g_bufB);
    cudaGetSymbolAddress((void**)&wTrk, g_wTrunk);
    cudaGetSymbolAddress((void**)&wCls, g_wCls);
    cudaGetSymbolAddress((void**)&wReg, g_wReg);
    cudaGetSymbolAddress((void**)&clsR, g_cls);
    cudaGetSymbolAddress((void**)&regR, g_reg);
    cudaGetSymbolAddress((void**)&scores, g_scores);
    cudaGetSymbolAddress((void**)&arg, g_arg);
    cudaGetSymbolAddress((void**)&loc, g_loc);
    cudaGetSymbolAddress((void**)&keys, g_keys);
    cudaGetSymbolAddress((void**)&tmpA, g_tmpA);
    cudaGetSymbolAddress((void**)&tmpB, g_tmpB);
    cudaGetSymbolAddress((void**)&mask, g_mask);
    cudaGetSymbolAddress((void**)&selBox, g_selBox);
    cudaGetSymbolAddress((void**)&topVal, g_topVal);
    cudaGetSymbolAddress((void**)&selCls, g_selCls);
    cudaGetSymbolAddress((void**)&keep, g_keep);

    static int smemSet = 0;
    if (!smemSet) {
        cudaFuncSetAttribute(conv_trunk_k, cudaFuncAttributeMaxDynamicSharedMemorySize, DYN_SMEM);
        cudaFuncSetAttribute(conv_head_k,  cudaFuncAttributeMaxDynamicSharedMemorySize, DYN_SMEM);
        smemSet = 1;
    }

    const int TRK = 4*256*9*256;
    transpose_trunk_k<<<CDIV(TRK,256), 256>>>(cls_w, wTrk);
    transpose_trunk_k<<<CDIV(TRK,256), 256>>>(reg_w, wTrk + TRK);
    transpose_head_k<<<CDIV(256*9*768,256), 256>>>(cls_hw, wCls, 720, 768);
    transpose_head_k<<<CDIV(256*9*128,256), 256>>>(reg_hw, wReg, 36, 128);

    dim3 gt(139, 2, 2);
    conv_trunk_k<<<gt, 256, DYN_SMEM>>>(f0,f1,f2,f3,f4, nullptr, bufA, wTrk, cls_b, reg_b, 0, 1);
    conv_trunk_k<<<gt, 256, DYN_SMEM>>>(f0,f1,f2,f3,f4, bufA,    bufB, wTrk, cls_b, reg_b, 1, 0);
    conv_trunk_k<<<gt, 256, DYN_SMEM>>>(f0,f1,f2,f3,f4, bufB,    bufA, wTrk, cls_b, reg_b, 2, 0);
    conv_trunk_k<<<gt, 256, DYN_SMEM>>>(f0,f1,f2,f3,f4, bufA,    bufB, wTrk, cls_b, reg_b, 3, 0);
    dim3 gh(139, 7, 1);
    conv_head_k<<<gh, 256, DYN_SMEM>>>(bufB, clsR, regR, wCls, wReg, cls_hb, reg_hb);

    score_key_k<<<N_SORT / 256, 256>>>(clsR, regR, scores, arg, loc, keys);

    bitonic_local_k<<<N_SORT / 2048, 1024>>>(keys);
    topk_merge_k<<<32, 512>>>(keys, tmpA, 2048);
    topk_merge_k<<<16, 512>>>(tmpA, tmpB, 1024);
    topk_merge_k<<< 8, 512>>>(tmpB, tmpA, 1024);
    topk_merge_k<<< 4, 512>>>(tmpA, tmpB, 1024);
    topk_merge_k<<< 2, 512>>>(tmpB, tmpA, 1024);
    topk_merge_k<<< 1, 512>>>(tmpA, tmpB, 1024);

    decode_k<<<CDIV(KTOP, 256), 256>>>(tmpB, scores, arg, loc, selBox, topVal, selCls);
    iou_mask_k<<<KTOP, 1024>>>(selBox, mask);
    nms_seq_k<<<1, 32>>>(mask, topVal, keep);
    output_k<<<CDIV(KTOP, 256), 256>>>(topVal, selCls, selBox, keep,
                                       (float*)d_out, out_size);
}